// round 1
// baseline (speedup 1.0000x reference)
#include <cuda_runtime.h>
#include <cuda_bf16.h>
#include <math.h>
#include <stdint.h>

// Problem constants
#define BSZ 4096
#define NN  8192          // N = 2*B
#define DD  512
#define INV_T 2.0f        // 1 / temperature (0.5)

// GEMM tiling
#define BM 128
#define BN 128
#define BK 32
#define PAD 8             // smem padding (bf16 elems) -> row stride 40 bf16 = 20 u32

// Scratch (static device allocations only — no cudaMalloc allowed)
__device__ __nv_bfloat16 g_hb[(size_t)NN * DD];        // 8 MB
__device__ float g_sim[(size_t)NN * NN];               // 256 MB
__device__ float g_rowval[NN];

// ---------------------------------------------------------------------------
// 1) fp32 -> bf16 convert of h = concat(h_i, h_j)
// ---------------------------------------------------------------------------
__global__ void convert_kernel(const float* __restrict__ hi,
                               const float* __restrict__ hj) {
    int idx = blockIdx.x * blockDim.x + threadIdx.x;
    if (idx < BSZ * DD) {
        g_hb[idx]            = __float2bfloat16(hi[idx]);
        g_hb[BSZ * DD + idx] = __float2bfloat16(hj[idx]);
    }
}

// ---------------------------------------------------------------------------
// 2) sim = hb @ hb^T  (raw dot; 1/T applied in reduce).
//    Warp-level mma.sync m16n8k16 bf16, fp32 accum.
//    CTA = 128x128 tile, 8 warps in 2(m) x 4(n) grid, warp tile 64x32.
// ---------------------------------------------------------------------------
__device__ __forceinline__ void mma_bf16(float c[4],
                                         const uint32_t a[4],
                                         const uint32_t b[2]) {
    asm volatile(
        "mma.sync.aligned.m16n8k16.row.col.f32.bf16.bf16.f32 "
        "{%0,%1,%2,%3}, {%4,%5,%6,%7}, {%8,%9}, {%0,%1,%2,%3};\n"
        : "+f"(c[0]), "+f"(c[1]), "+f"(c[2]), "+f"(c[3])
        : "r"(a[0]), "r"(a[1]), "r"(a[2]), "r"(a[3]),
          "r"(b[0]), "r"(b[1]));
}

__global__ __launch_bounds__(256) void gemm_kernel() {
    __shared__ __nv_bfloat16 As[BM][BK + PAD];
    __shared__ __nv_bfloat16 Bs[BN][BK + PAD];

    const int tid  = threadIdx.x;
    const int warp = tid >> 5;
    const int lane = tid & 31;
    const int warpM = warp >> 2;   // 0..1
    const int warpN = warp & 3;    // 0..3
    const int grp = lane >> 2;     // 0..7
    const int tg  = lane & 3;      // 0..3

    const int rowBase = blockIdx.y * BM;
    const int colBase = blockIdx.x * BN;

    float acc[4][4][4];
    #pragma unroll
    for (int mi = 0; mi < 4; mi++)
        #pragma unroll
        for (int ni = 0; ni < 4; ni++)
            #pragma unroll
            for (int r = 0; r < 4; r++) acc[mi][ni][r] = 0.0f;

    const uint32_t* As32 = reinterpret_cast<const uint32_t*>(&As[0][0]);
    const uint32_t* Bs32 = reinterpret_cast<const uint32_t*>(&Bs[0][0]);
    const int S32 = (BK + PAD) / 2;  // 20 u32 per row

    #pragma unroll 1
    for (int kb = 0; kb < DD / BK; kb++) {
        const int k0g = kb * BK;

        // Load A and B tiles (128x32 bf16 each) with uint4 (8 bf16) vectors.
        #pragma unroll
        for (int l = 0; l < 2; l++) {
            int lin = tid + l * 256;     // 0..511
            int r   = lin >> 2;          // 0..127
            int c4  = lin & 3;           // 0..3
            const uint4* srcA = reinterpret_cast<const uint4*>(
                g_hb + (size_t)(rowBase + r) * DD + k0g + c4 * 8);
            *reinterpret_cast<uint4*>(&As[r][c4 * 8]) = *srcA;
            const uint4* srcB = reinterpret_cast<const uint4*>(
                g_hb + (size_t)(colBase + r) * DD + k0g + c4 * 8);
            *reinterpret_cast<uint4*>(&Bs[r][c4 * 8]) = *srcB;
        }
        __syncthreads();

        #pragma unroll
        for (int ks = 0; ks < 2; ks++) {
            const int kc = ks * 8;  // u32 offset within row (16 bf16)

            uint32_t af[4][4];
            #pragma unroll
            for (int mi = 0; mi < 4; mi++) {
                int r0 = warpM * 64 + mi * 16 + grp;
                af[mi][0] = As32[(size_t)r0 * S32 + kc + tg];
                af[mi][1] = As32[(size_t)(r0 + 8) * S32 + kc + tg];
                af[mi][2] = As32[(size_t)r0 * S32 + kc + tg + 4];
                af[mi][3] = As32[(size_t)(r0 + 8) * S32 + kc + tg + 4];
            }
            uint32_t bf[4][2];
            #pragma unroll
            for (int ni = 0; ni < 4; ni++) {
                int rb = warpN * 32 + ni * 8 + grp;
                bf[ni][0] = Bs32[(size_t)rb * S32 + kc + tg];
                bf[ni][1] = Bs32[(size_t)rb * S32 + kc + tg + 4];
            }
            #pragma unroll
            for (int mi = 0; mi < 4; mi++)
                #pragma unroll
                for (int ni = 0; ni < 4; ni++)
                    mma_bf16(acc[mi][ni], af[mi], bf[ni]);
        }
        __syncthreads();
    }

    // Epilogue: write fp32 tile
    #pragma unroll
    for (int mi = 0; mi < 4; mi++) {
        #pragma unroll
        for (int ni = 0; ni < 4; ni++) {
            int r0 = rowBase + warpM * 64 + mi * 16 + grp;
            int c  = colBase + warpN * 32 + ni * 8 + tg * 2;
            *reinterpret_cast<float2*>(&g_sim[(size_t)r0 * NN + c]) =
                make_float2(acc[mi][ni][0], acc[mi][ni][1]);
            *reinterpret_cast<float2*>(&g_sim[(size_t)(r0 + 8) * NN + c]) =
                make_float2(acc[mi][ni][2], acc[mi][ni][3]);
        }
    }
}

// ---------------------------------------------------------------------------
// 3) Per-row masked LSE: exclude diagonal, pos = sim[i, (i+B) mod N].
//    One CTA per row, 256 threads, 32 elements per thread in registers.
// ---------------------------------------------------------------------------
__global__ __launch_bounds__(256) void row_lse_kernel() {
    const int i = blockIdx.x;
    const int t = threadIdx.x;
    const float* __restrict__ row = g_sim + (size_t)i * NN;

    float v[32];
    #pragma unroll
    for (int k = 0; k < 32; k++) {
        int j = k * 256 + t;
        float x = row[j] * INV_T;
        v[k] = (j == i) ? -INFINITY : x;
    }

    float m = -INFINITY;
    #pragma unroll
    for (int k = 0; k < 32; k++) m = fmaxf(m, v[k]);

    __shared__ float sm[256];
    sm[t] = m;
    __syncthreads();
    #pragma unroll
    for (int s = 128; s > 0; s >>= 1) {
        if (t < s) sm[t] = fmaxf(sm[t], sm[t + s]);
        __syncthreads();
    }
    m = sm[0];
    __syncthreads();

    float s = 0.0f;
    #pragma unroll
    for (int k = 0; k < 32; k++) s += expf(v[k] - m);  // exp(-inf)=0 masks diag

    sm[t] = s;
    __syncthreads();
    #pragma unroll
    for (int st = 128; st > 0; st >>= 1) {
        if (t < st) sm[t] += sm[t + st];
        __syncthreads();
    }

    if (t == 0) {
        float lse = m + logf(sm[0]);
        int p = (i < BSZ) ? (i + BSZ) : (i - BSZ);
        g_rowval[i] = lse - row[p] * INV_T;
    }
}

// ---------------------------------------------------------------------------
// 4) Deterministic final reduction: loss = sum(rowval) / N
// ---------------------------------------------------------------------------
__global__ __launch_bounds__(256) void final_kernel(float* __restrict__ out) {
    const int t = threadIdx.x;
    float s = 0.0f;
    #pragma unroll
    for (int k = 0; k < 32; k++) s += g_rowval[k * 256 + t];

    __shared__ float sm[256];
    sm[t] = s;
    __syncthreads();
    #pragma unroll
    for (int st = 128; st > 0; st >>= 1) {
        if (t < st) sm[t] += sm[t + st];
        __syncthreads();
    }
    if (t == 0) out[0] = sm[0] / (float)NN;
}

// ---------------------------------------------------------------------------
extern "C" void kernel_launch(void* const* d_in, const int* in_sizes, int n_in,
                              void* d_out, int out_size) {
    const float* hi = (const float*)d_in[0];
    const float* hj = (const float*)d_in[1];
    float* out = (float*)d_out;

    convert_kernel<<<(BSZ * DD + 255) / 256, 256>>>(hi, hj);

    dim3 grid(NN / BN, NN / BM);
    gemm_kernel<<<grid, 256>>>();

    row_lse_kernel<<<NN, 256>>>();
    final_kernel<<<1, 256>>>(out);
}

// round 2
// speedup vs baseline: 2.4222x; 2.4222x over previous
#include <cuda_runtime.h>
#include <cuda_bf16.h>
#include <math.h>
#include <stdint.h>

// Problem constants
#define BSZ 4096
#define NN  8192          // N = 2*B
#define DD  512
#define INV_T 2.0f        // 1 / temperature

// GEMM tiling
#define BM 128
#define BN 128
#define BK 32
#define PAD 8             // bf16 padding -> row stride 40 bf16 = 20 u32
#define NT 64             // NN / 128 column blocks
#define NTILES 2080       // 64*65/2 upper-triangular tiles

#define FULLMASK 0xFFFFFFFFu
#define NEGINF (-INFINITY)

// Scratch (static device allocations only)
__device__ __nv_bfloat16 g_hb[(size_t)NN * DD];     // 8 MB
__device__ float2 g_part[(size_t)NN * NT];          // 4 MB (max,sumexp) partials
__device__ float g_pos[NN];
__device__ float g_rowval[NN];

// ---------------------------------------------------------------------------
// 1) fp32 -> bf16 convert of h = concat(h_i, h_j)
// ---------------------------------------------------------------------------
__global__ void convert_kernel(const float* __restrict__ hi,
                               const float* __restrict__ hj) {
    int idx = blockIdx.x * blockDim.x + threadIdx.x;
    if (idx < BSZ * DD) {
        g_hb[idx]            = __float2bfloat16(hi[idx]);
        g_hb[BSZ * DD + idx] = __float2bfloat16(hj[idx]);
    }
}

// ---------------------------------------------------------------------------
// mma.sync m16n8k16 bf16, fp32 accum
// ---------------------------------------------------------------------------
__device__ __forceinline__ void mma_bf16(float c[4],
                                         const uint32_t a[4],
                                         const uint32_t b[2]) {
    asm volatile(
        "mma.sync.aligned.m16n8k16.row.col.f32.bf16.bf16.f32 "
        "{%0,%1,%2,%3}, {%4,%5,%6,%7}, {%8,%9}, {%0,%1,%2,%3};\n"
        : "+f"(c[0]), "+f"(c[1]), "+f"(c[2]), "+f"(c[3])
        : "r"(a[0]), "r"(a[1]), "r"(a[2]), "r"(a[3]),
          "r"(b[0]), "r"(b[1]));
}

__device__ __forceinline__ void cp_async16(void* smem_dst, const void* gmem_src) {
    uint32_t s = (uint32_t)__cvta_generic_to_shared(smem_dst);
    asm volatile("cp.async.cg.shared.global [%0], [%1], 16;\n"
                 :: "r"(s), "l"(gmem_src));
}

__device__ __forceinline__ float2 lse_combine(float2 a, float2 b) {
    float m = fmaxf(a.x, b.x);
    float s = a.y * __expf(a.x - m) + b.y * __expf(b.x - m);
    return make_float2(m, s);
}

// ---------------------------------------------------------------------------
// 2) Fused GEMM (upper-triangular tiles only) + per-tile masked LSE partials.
//    CTA = 128x128 tile of sim, 8 warps in 2(m) x 4(n), warp tile 64x32.
//    Row side -> g_part[row][tn]; col side (symmetry) -> g_part[col][tm].
// ---------------------------------------------------------------------------
__global__ __launch_bounds__(256) void gemm_fused_kernel() {
    __shared__ __nv_bfloat16 As[2][BM][BK + PAD];
    __shared__ __nv_bfloat16 Bs[2][BN][BK + PAD];
    __shared__ float2 rowRed[128][4];
    __shared__ float2 colRed[128][2];

    // Decode upper-triangular tile index: start(t) = t*(129-t)/2
    const int idx = blockIdx.x;
    int tm = (int)((129.0f - sqrtf(129.0f * 129.0f - 8.0f * (float)idx)) * 0.5f);
    while (tm > 0 && tm * (129 - tm) / 2 > idx) tm--;
    while ((tm + 1) * (129 - (tm + 1)) / 2 <= idx) tm++;
    const int tn = tm + (idx - tm * (129 - tm) / 2);

    const int rowBase = tm * BM;
    const int colBase = tn * BN;
    const bool diagTile = (tm == tn);
    const bool posTile  = (colBase - rowBase == BSZ);

    const int tid  = threadIdx.x;
    const int warp = tid >> 5;
    const int lane = tid & 31;
    const int warpM = warp >> 2;   // 0..1
    const int warpN = warp & 3;    // 0..3
    const int grp = lane >> 2;     // 0..7
    const int tg  = lane & 3;      // 0..3

    float acc[4][4][4];
    #pragma unroll
    for (int mi = 0; mi < 4; mi++)
        #pragma unroll
        for (int ni = 0; ni < 4; ni++)
            #pragma unroll
            for (int r = 0; r < 4; r++) acc[mi][ni][r] = 0.0f;

    const int S32 = (BK + PAD) / 2;  // 20 u32 per row
    const int r_ld  = tid >> 2;      // load row 0 (tid<512 handled by l loop)
    const int c4_ld = tid & 3;

    // Prefetch stage 0
    {
        const int k0g = 0;
        #pragma unroll
        for (int l = 0; l < 2; l++) {
            int lin = tid + l * 256;
            int r = lin >> 2, c4 = lin & 3;
            cp_async16(&As[0][r][c4 * 8],
                       g_hb + (size_t)(rowBase + r) * DD + k0g + c4 * 8);
            cp_async16(&Bs[0][r][c4 * 8],
                       g_hb + (size_t)(colBase + r) * DD + k0g + c4 * 8);
        }
        asm volatile("cp.async.commit_group;\n");
    }

    #pragma unroll 1
    for (int kb = 0; kb < DD / BK; kb++) {
        const int buf = kb & 1;
        if (kb + 1 < DD / BK) {
            const int k0g = (kb + 1) * BK;
            const int nbuf = (kb + 1) & 1;
            #pragma unroll
            for (int l = 0; l < 2; l++) {
                int lin = tid + l * 256;
                int r = lin >> 2, c4 = lin & 3;
                cp_async16(&As[nbuf][r][c4 * 8],
                           g_hb + (size_t)(rowBase + r) * DD + k0g + c4 * 8);
                cp_async16(&Bs[nbuf][r][c4 * 8],
                           g_hb + (size_t)(colBase + r) * DD + k0g + c4 * 8);
            }
            asm volatile("cp.async.commit_group;\n");
            asm volatile("cp.async.wait_group 1;\n");
        } else {
            asm volatile("cp.async.wait_group 0;\n");
        }
        __syncthreads();

        const uint32_t* As32 = reinterpret_cast<const uint32_t*>(&As[buf][0][0]);
        const uint32_t* Bs32 = reinterpret_cast<const uint32_t*>(&Bs[buf][0][0]);

        #pragma unroll
        for (int ks = 0; ks < 2; ks++) {
            const int kc = ks * 8;
            uint32_t af[4][4];
            #pragma unroll
            for (int mi = 0; mi < 4; mi++) {
                int r0 = warpM * 64 + mi * 16 + grp;
                af[mi][0] = As32[(size_t)r0 * S32 + kc + tg];
                af[mi][1] = As32[(size_t)(r0 + 8) * S32 + kc + tg];
                af[mi][2] = As32[(size_t)r0 * S32 + kc + tg + 4];
                af[mi][3] = As32[(size_t)(r0 + 8) * S32 + kc + tg + 4];
            }
            uint32_t bf[4][2];
            #pragma unroll
            for (int ni = 0; ni < 4; ni++) {
                int rb = warpN * 32 + ni * 8 + grp;
                bf[ni][0] = Bs32[(size_t)rb * S32 + kc + tg];
                bf[ni][1] = Bs32[(size_t)rb * S32 + kc + tg + 4];
            }
            #pragma unroll
            for (int mi = 0; mi < 4; mi++)
                #pragma unroll
                for (int ni = 0; ni < 4; ni++)
                    mma_bf16(acc[mi][ni], af[mi], bf[ni]);
        }
        __syncthreads();
    }

    // ---- Epilogue: scale, mask diagonal, extract positive pairs ----
    #pragma unroll
    for (int mi = 0; mi < 4; mi++) {
        const int gr_a = rowBase + warpM * 64 + mi * 16 + grp;
        const int gr_b = gr_a + 8;
        #pragma unroll
        for (int ni = 0; ni < 4; ni++) {
            const int gc0 = colBase + warpN * 32 + ni * 8 + tg * 2;
            const int gc1 = gc0 + 1;
            float v0 = acc[mi][ni][0] * INV_T;
            float v1 = acc[mi][ni][1] * INV_T;
            float v2 = acc[mi][ni][2] * INV_T;
            float v3 = acc[mi][ni][3] * INV_T;
            if (posTile) {   // colBase - rowBase == BSZ: pos entries live here
                if (gc0 == gr_a + BSZ) { g_pos[gr_a] = v0; g_pos[gc0] = v0; }
                if (gc1 == gr_a + BSZ) { g_pos[gr_a] = v1; g_pos[gc1] = v1; }
                if (gc0 == gr_b + BSZ) { g_pos[gr_b] = v2; g_pos[gc0] = v2; }
                if (gc1 == gr_b + BSZ) { g_pos[gr_b] = v3; g_pos[gc1] = v3; }
            }
            if (diagTile) {
                if (gr_a == gc0) v0 = NEGINF;
                if (gr_a == gc1) v1 = NEGINF;
                if (gr_b == gc0) v2 = NEGINF;
                if (gr_b == gc1) v3 = NEGINF;
            }
            acc[mi][ni][0] = v0; acc[mi][ni][1] = v1;
            acc[mi][ni][2] = v2; acc[mi][ni][3] = v3;
        }
    }

    // ---- Row-side reduction (m rows over this tile's 128 n-cols) ----
    #pragma unroll
    for (int mi = 0; mi < 4; mi++) {
        float mA = NEGINF, mB = NEGINF;
        #pragma unroll
        for (int ni = 0; ni < 4; ni++) {
            mA = fmaxf(mA, fmaxf(acc[mi][ni][0], acc[mi][ni][1]));
            mB = fmaxf(mB, fmaxf(acc[mi][ni][2], acc[mi][ni][3]));
        }
        mA = fmaxf(mA, __shfl_xor_sync(FULLMASK, mA, 1));
        mA = fmaxf(mA, __shfl_xor_sync(FULLMASK, mA, 2));
        mB = fmaxf(mB, __shfl_xor_sync(FULLMASK, mB, 1));
        mB = fmaxf(mB, __shfl_xor_sync(FULLMASK, mB, 2));
        float sA = 0.0f, sB = 0.0f;
        #pragma unroll
        for (int ni = 0; ni < 4; ni++) {
            sA += __expf(acc[mi][ni][0] - mA) + __expf(acc[mi][ni][1] - mA);
            sB += __expf(acc[mi][ni][2] - mB) + __expf(acc[mi][ni][3] - mB);
        }
        sA += __shfl_xor_sync(FULLMASK, sA, 1);
        sA += __shfl_xor_sync(FULLMASK, sA, 2);
        sB += __shfl_xor_sync(FULLMASK, sB, 1);
        sB += __shfl_xor_sync(FULLMASK, sB, 2);
        if (tg == 0) {
            rowRed[warpM * 64 + mi * 16 + grp][warpN]     = make_float2(mA, sA);
            rowRed[warpM * 64 + mi * 16 + grp + 8][warpN] = make_float2(mB, sB);
        }
    }

    // ---- Col-side reduction (n rows via symmetry), skip on diagonal tile ----
    if (!diagTile) {
        #pragma unroll
        for (int ni = 0; ni < 4; ni++) {
            float m0 = NEGINF, m1 = NEGINF;
            #pragma unroll
            for (int mi = 0; mi < 4; mi++) {
                m0 = fmaxf(m0, fmaxf(acc[mi][ni][0], acc[mi][ni][2]));
                m1 = fmaxf(m1, fmaxf(acc[mi][ni][1], acc[mi][ni][3]));
            }
            #pragma unroll
            for (int d = 4; d < 32; d <<= 1) {
                m0 = fmaxf(m0, __shfl_xor_sync(FULLMASK, m0, d));
                m1 = fmaxf(m1, __shfl_xor_sync(FULLMASK, m1, d));
            }
            float s0 = 0.0f, s1 = 0.0f;
            #pragma unroll
            for (int mi = 0; mi < 4; mi++) {
                s0 += __expf(acc[mi][ni][0] - m0) + __expf(acc[mi][ni][2] - m0);
                s1 += __expf(acc[mi][ni][1] - m1) + __expf(acc[mi][ni][3] - m1);
            }
            #pragma unroll
            for (int d = 4; d < 32; d <<= 1) {
                s0 += __shfl_xor_sync(FULLMASK, s0, d);
                s1 += __shfl_xor_sync(FULLMASK, s1, d);
            }
            if (grp == 0) {
                colRed[warpN * 32 + ni * 8 + tg * 2][warpM]     = make_float2(m0, s0);
                colRed[warpN * 32 + ni * 8 + tg * 2 + 1][warpM] = make_float2(m1, s1);
            }
        }
    }
    __syncthreads();

    // ---- Final per-tile combine + store partials ----
    if (tid < 128) {
        float2 p = rowRed[tid][0];
        p = lse_combine(p, rowRed[tid][1]);
        p = lse_combine(p, rowRed[tid][2]);
        p = lse_combine(p, rowRed[tid][3]);
        g_part[(size_t)(rowBase + tid) * NT + tn] = p;
    } else if (!diagTile) {
        int c = tid - 128;
        float2 p = lse_combine(colRed[c][0], colRed[c][1]);
        g_part[(size_t)(colBase + c) * NT + tm] = p;
    }
}

// ---------------------------------------------------------------------------
// 3) Per-row combine of 64 partials: lse = m + log(s); rowval = lse - pos
//    One warp per row.
// ---------------------------------------------------------------------------
__global__ __launch_bounds__(256) void combine_kernel() {
    const int row  = blockIdx.x * 8 + (threadIdx.x >> 5);
    const int lane = threadIdx.x & 31;
    float2 p = g_part[(size_t)row * NT + lane * 2];
    float2 q = g_part[(size_t)row * NT + lane * 2 + 1];
    p = lse_combine(p, q);
    float m = p.x, s = p.y;
    #pragma unroll
    for (int d = 1; d < 32; d <<= 1) {
        float mo = __shfl_xor_sync(FULLMASK, m, d);
        float so = __shfl_xor_sync(FULLMASK, s, d);
        float mm = fmaxf(m, mo);
        s = s * __expf(m - mm) + so * __expf(mo - mm);
        m = mm;
    }
    if (lane == 0) g_rowval[row] = m + logf(s) - g_pos[row];
}

// ---------------------------------------------------------------------------
// 4) Deterministic final reduction: loss = sum(rowval) / N
// ---------------------------------------------------------------------------
__global__ __launch_bounds__(256) void final_kernel(float* __restrict__ out) {
    const int t = threadIdx.x;
    float s = 0.0f;
    #pragma unroll
    for (int k = 0; k < 32; k++) s += g_rowval[k * 256 + t];

    __shared__ float sm[256];
    sm[t] = s;
    __syncthreads();
    #pragma unroll
    for (int st = 128; st > 0; st >>= 1) {
        if (t < st) sm[t] += sm[t + st];
        __syncthreads();
    }
    if (t == 0) out[0] = sm[0] / (float)NN;
}

// ---------------------------------------------------------------------------
extern "C" void kernel_launch(void* const* d_in, const int* in_sizes, int n_in,
                              void* d_out, int out_size) {
    const float* hi = (const float*)d_in[0];
    const float* hj = (const float*)d_in[1];
    float* out = (float*)d_out;

    convert_kernel<<<(BSZ * DD + 255) / 256, 256>>>(hi, hj);
    gemm_fused_kernel<<<NTILES, 256>>>();
    combine_kernel<<<NN / 8, 256>>>();
    final_kernel<<<1, 256>>>(out);
}

// round 5
// speedup vs baseline: 2.4279x; 1.0024x over previous
#include <cuda_runtime.h>
#include <cuda_bf16.h>
#include <math.h>
#include <stdint.h>

// Problem constants
#define BSZ 4096
#define NN  8192          // N = 2*B
#define DD  512
#define INV_T 2.0f        // 1 / temperature

// GEMM tiling
#define BM 128
#define BN 128
#define BK 64             // 128B rows -> SW128 swizzle, no padding
#define NT 64             // NN / 128 column blocks
#define NTILES 2080       // 64*65/2 upper-triangular tiles

#define FULLMASK 0xFFFFFFFFu
#define NEGINF (-INFINITY)

// Dynamic smem: A0 | A1 | B0 | B1, each 128x64 bf16 = 16KB. Total 64KB.
#define TILE_ELEMS (BM * BK)          // 8192 bf16 = 16384 B
#define SMEM_BYTES (4 * TILE_ELEMS * 2)

// Scratch (static device allocations only)
__device__ __nv_bfloat16 g_hb[(size_t)NN * DD];     // 8 MB
__device__ float2 g_part[(size_t)NN * NT];          // 4 MB (max,sumexp) partials
__device__ float g_pos[NN];
__device__ float g_rowval[NN];

// ---------------------------------------------------------------------------
// helpers
// ---------------------------------------------------------------------------
__device__ __forceinline__ uint32_t smem_u32(const void* p) {
    uint32_t a;
    asm("{ .reg .u64 t; cvta.to.shared.u64 t, %1; cvt.u32.u64 %0, t; }"
        : "=r"(a) : "l"(p));
    return a;
}

__device__ __forceinline__ void mma_bf16(float c[4],
                                         const uint32_t a[4],
                                         uint32_t b0, uint32_t b1) {
    asm volatile(
        "mma.sync.aligned.m16n8k16.row.col.f32.bf16.bf16.f32 "
        "{%0,%1,%2,%3}, {%4,%5,%6,%7}, {%8,%9}, {%0,%1,%2,%3};\n"
        : "+f"(c[0]), "+f"(c[1]), "+f"(c[2]), "+f"(c[3])
        : "r"(a[0]), "r"(a[1]), "r"(a[2]), "r"(a[3]),
          "r"(b0), "r"(b1));
}

__device__ __forceinline__ void ldsm_x4(uint32_t r[4], uint32_t addr) {
    asm volatile(
        "ldmatrix.sync.aligned.m8n8.x4.shared.b16 {%0,%1,%2,%3}, [%4];"
        : "=r"(r[0]), "=r"(r[1]), "=r"(r[2]), "=r"(r[3]) : "r"(addr));
}

__device__ __forceinline__ void cp_async16(uint32_t smem_dst, const void* g) {
    asm volatile("cp.async.cg.shared.global [%0], [%1], 16;\n"
                 :: "r"(smem_dst), "l"(g));
}

__device__ __forceinline__ float2 lse_combine(float2 a, float2 b) {
    float m = fmaxf(a.x, b.x);
    float s = a.y * __expf(a.x - m) + b.y * __expf(b.x - m);
    return make_float2(m, s);
}

__device__ __forceinline__ uint32_t sw128(uint32_t off) {
    return off ^ ((off >> 3) & 0x70);
}

// ---------------------------------------------------------------------------
// 1) fp32 -> bf16 convert (vectorized)
// ---------------------------------------------------------------------------
__global__ void convert_kernel(const float4* __restrict__ hi,
                               const float4* __restrict__ hj) {
    int idx = blockIdx.x * blockDim.x + threadIdx.x;   // 0 .. BSZ*DD/4-1
    if (idx < BSZ * DD / 4) {
        float4 a = hi[idx];
        float4 b = hj[idx];
        __nv_bfloat162 pa0 = __floats2bfloat162_rn(a.x, a.y);
        __nv_bfloat162 pa1 = __floats2bfloat162_rn(a.z, a.w);
        __nv_bfloat162 pb0 = __floats2bfloat162_rn(b.x, b.y);
        __nv_bfloat162 pb1 = __floats2bfloat162_rn(b.z, b.w);
        __nv_bfloat162* dst_a = reinterpret_cast<__nv_bfloat162*>(g_hb);
        __nv_bfloat162* dst_b =
            reinterpret_cast<__nv_bfloat162*>(g_hb + (size_t)BSZ * DD);
        dst_a[idx * 2]     = pa0;
        dst_a[idx * 2 + 1] = pa1;
        dst_b[idx * 2]     = pb0;
        dst_b[idx * 2 + 1] = pb1;
    }
}

// ---------------------------------------------------------------------------
// 2) Fused GEMM (upper-triangular tiles) + per-tile masked LSE partials.
//    CTA = 128x128 tile, 8 warps 2(m) x 4(n), warp tile 64x32.
//    ldmatrix.x4 fragment loads from SW128-swizzled smem, BK=64, cp.async DB.
// ---------------------------------------------------------------------------
__global__ __launch_bounds__(256) void gemm_fused_kernel() {
    extern __shared__ __nv_bfloat16 dsm[];
    __shared__ float2 rowRed[128][4];
    __shared__ float2 colRed[128][2];

    const uint32_t smemBase = smem_u32(dsm);

    // Decode upper-triangular tile index
    const int idx = blockIdx.x;
    int tm = (int)((129.0f - sqrtf(129.0f * 129.0f - 8.0f * (float)idx)) * 0.5f);
    while (tm > 0 && tm * (129 - tm) / 2 > idx) tm--;
    while ((tm + 1) * (129 - (tm + 1)) / 2 <= idx) tm++;
    const int tn = tm + (idx - tm * (129 - tm) / 2);

    const int rowBase = tm * BM;
    const int colBase = tn * BN;
    const bool diagTile = (tm == tn);
    const bool posTile  = (colBase - rowBase == BSZ);

    const int tid  = threadIdx.x;
    const int warp = tid >> 5;
    const int lane = tid & 31;
    const int warpM = warp >> 2;   // 0..1
    const int warpN = warp & 3;    // 0..3
    const int grp = lane >> 2;     // 0..7
    const int tg  = lane & 3;      // 0..3

    float acc[4][4][4];
    #pragma unroll
    for (int mi = 0; mi < 4; mi++)
        #pragma unroll
        for (int ni = 0; ni < 4; ni++)
            #pragma unroll
            for (int r = 0; r < 4; r++) acc[mi][ni][r] = 0.0f;

    // chunk loader: K-chunk kb (64 bf16 wide) into buffer buf
    auto load_chunk = [&](int kb, int buf) {
        const int kg = kb * BK;
        const uint32_t aB = smemBase + buf * (TILE_ELEMS * 2);
        const uint32_t bB = smemBase + (2 + buf) * (TILE_ELEMS * 2);
        #pragma unroll
        for (int j = 0; j < 4; j++) {
            int lin = tid + j * 256;      // 0..1023
            int r   = lin >> 3;           // 0..127
            int c16 = lin & 7;            // 16B column
            uint32_t sw = sw128(r * 128 + c16 * 16);
            cp_async16(aB + sw, g_hb + (size_t)(rowBase + r) * DD + kg + c16 * 8);
            cp_async16(bB + sw, g_hb + (size_t)(colBase + r) * DD + kg + c16 * 8);
        }
        asm volatile("cp.async.commit_group;\n" ::: "memory");
    };

    load_chunk(0, 0);

    // per-lane ldmatrix row/col components (within tile)
    const int lrow = lane & 15;
    const int lhi  = (lane >> 4) * 16;   // byte offset selecting k8 half

    #pragma unroll 1
    for (int kb = 0; kb < DD / BK; kb++) {
        const int buf = kb & 1;
        if (kb + 1 < DD / BK) {
            load_chunk(kb + 1, (kb + 1) & 1);
            asm volatile("cp.async.wait_group 1;\n" ::: "memory");
        } else {
            asm volatile("cp.async.wait_group 0;\n" ::: "memory");
        }
        __syncthreads();

        const uint32_t aB = smemBase + buf * (TILE_ELEMS * 2);
        const uint32_t bB = smemBase + (2 + buf) * (TILE_ELEMS * 2);

        #pragma unroll
        for (int ks = 0; ks < 4; ks++) {
            const int cb = lhi + ks * 32;

            uint32_t af[4][4];
            #pragma unroll
            for (int mi = 0; mi < 4; mi++) {
                uint32_t off = (warpM * 64 + mi * 16 + lrow) * 128 + cb;
                ldsm_x4(af[mi], aB + sw128(off));
            }
            uint32_t bq[2][4];
            #pragma unroll
            for (int n2 = 0; n2 < 2; n2++) {
                uint32_t off = (warpN * 32 + n2 * 16 + lrow) * 128 + cb;
                ldsm_x4(bq[n2], bB + sw128(off));
            }
            #pragma unroll
            for (int mi = 0; mi < 4; mi++)
                #pragma unroll
                for (int ni = 0; ni < 4; ni++)
                    mma_bf16(acc[mi][ni], af[mi],
                             bq[ni >> 1][ni & 1], bq[ni >> 1][(ni & 1) + 2]);
        }
        __syncthreads();
    }

    // ---- Epilogue: scale, mask diagonal, extract positive pairs ----
    #pragma unroll
    for (int mi = 0; mi < 4; mi++) {
        const int gr_a = rowBase + warpM * 64 + mi * 16 + grp;
        const int gr_b = gr_a + 8;
        #pragma unroll
        for (int ni = 0; ni < 4; ni++) {
            const int gc0 = colBase + warpN * 32 + ni * 8 + tg * 2;
            const int gc1 = gc0 + 1;
            float v0 = acc[mi][ni][0] * INV_T;
            float v1 = acc[mi][ni][1] * INV_T;
            float v2 = acc[mi][ni][2] * INV_T;
            float v3 = acc[mi][ni][3] * INV_T;
            if (posTile) {
                if (gc0 == gr_a + BSZ) { g_pos[gr_a] = v0; g_pos[gc0] = v0; }
                if (gc1 == gr_a + BSZ) { g_pos[gr_a] = v1; g_pos[gc1] = v1; }
                if (gc0 == gr_b + BSZ) { g_pos[gr_b] = v2; g_pos[gc0] = v2; }
                if (gc1 == gr_b + BSZ) { g_pos[gr_b] = v3; g_pos[gc1] = v3; }
            }
            if (diagTile) {
                if (gr_a == gc0) v0 = NEGINF;
                if (gr_a == gc1) v1 = NEGINF;
                if (gr_b == gc0) v2 = NEGINF;
                if (gr_b == gc1) v3 = NEGINF;
            }
            acc[mi][ni][0] = v0; acc[mi][ni][1] = v1;
            acc[mi][ni][2] = v2; acc[mi][ni][3] = v3;
        }
    }

    // ---- Row-side reduction ----
    #pragma unroll
    for (int mi = 0; mi < 4; mi++) {
        float mA = NEGINF, mB = NEGINF;
        #pragma unroll
        for (int ni = 0; ni < 4; ni++) {
            mA = fmaxf(mA, fmaxf(acc[mi][ni][0], acc[mi][ni][1]));
            mB = fmaxf(mB, fmaxf(acc[mi][ni][2], acc[mi][ni][3]));
        }
        mA = fmaxf(mA, __shfl_xor_sync(FULLMASK, mA, 1));
        mA = fmaxf(mA, __shfl_xor_sync(FULLMASK, mA, 2));
        mB = fmaxf(mB, __shfl_xor_sync(FULLMASK, mB, 1));
        mB = fmaxf(mB, __shfl_xor_sync(FULLMASK, mB, 2));
        float sA = 0.0f, sB = 0.0f;
        #pragma unroll
        for (int ni = 0; ni < 4; ni++) {
            sA += __expf(acc[mi][ni][0] - mA) + __expf(acc[mi][ni][1] - mA);
            sB += __expf(acc[mi][ni][2] - mB) + __expf(acc[mi][ni][3] - mB);
        }
        sA += __shfl_xor_sync(FULLMASK, sA, 1);
        sA += __shfl_xor_sync(FULLMASK, sA, 2);
        sB += __shfl_xor_sync(FULLMASK, sB, 1);
        sB += __shfl_xor_sync(FULLMASK, sB, 2);
        if (tg == 0) {
            rowRed[warpM * 64 + mi * 16 + grp][warpN]     = make_float2(mA, sA);
            rowRed[warpM * 64 + mi * 16 + grp + 8][warpN] = make_float2(mB, sB);
        }
    }

    // ---- Col-side reduction (symmetry) ----
    if (!diagTile) {
        #pragma unroll
        for (int ni = 0; ni < 4; ni++) {
            float m0 = NEGINF, m1 = NEGINF;
            #pragma unroll
            for (int mi = 0; mi < 4; mi++) {
                m0 = fmaxf(m0, fmaxf(acc[mi][ni][0], acc[mi][ni][2]));
                m1 = fmaxf(m1, fmaxf(acc[mi][ni][1], acc[mi][ni][3]));
            }
            #pragma unroll
            for (int d = 4; d < 32; d <<= 1) {
                m0 = fmaxf(m0, __shfl_xor_sync(FULLMASK, m0, d));
                m1 = fmaxf(m1, __shfl_xor_sync(FULLMASK, m1, d));
            }
            float s0 = 0.0f, s1 = 0.0f;
            #pragma unroll
            for (int mi = 0; mi < 4; mi++) {
                s0 += __expf(acc[mi][ni][0] - m0) + __expf(acc[mi][ni][2] - m0);
                s1 += __expf(acc[mi][ni][1] - m1) + __expf(acc[mi][ni][3] - m1);
            }
            #pragma unroll
            for (int d = 4; d < 32; d <<= 1) {
                s0 += __shfl_xor_sync(FULLMASK, s0, d);
                s1 += __shfl_xor_sync(FULLMASK, s1, d);
            }
            if (grp == 0) {
                colRed[warpN * 32 + ni * 8 + tg * 2][warpM]     = make_float2(m0, s0);
                colRed[warpN * 32 + ni * 8 + tg * 2 + 1][warpM] = make_float2(m1, s1);
            }
        }
    }
    __syncthreads();

    // ---- Store partials ----
    if (tid < 128) {
        float2 p = rowRed[tid][0];
        p = lse_combine(p, rowRed[tid][1]);
        p = lse_combine(p, rowRed[tid][2]);
        p = lse_combine(p, rowRed[tid][3]);
        g_part[(size_t)(rowBase + tid) * NT + tn] = p;
    } else if (!diagTile) {
        int c = tid - 128;
        float2 p = lse_combine(colRed[c][0], colRed[c][1]);
        g_part[(size_t)(colBase + c) * NT + tm] = p;
    }
}

// ---------------------------------------------------------------------------
// 3) Per-row combine of 64 partials
// ---------------------------------------------------------------------------
__global__ __launch_bounds__(256) void combine_kernel() {
    const int row  = blockIdx.x * 8 + (threadIdx.x >> 5);
    const int lane = threadIdx.x & 31;
    float2 p = g_part[(size_t)row * NT + lane * 2];
    float2 q = g_part[(size_t)row * NT + lane * 2 + 1];
    p = lse_combine(p, q);
    float m = p.x, s = p.y;
    #pragma unroll
    for (int d = 1; d < 32; d <<= 1) {
        float mo = __shfl_xor_sync(FULLMASK, m, d);
        float so = __shfl_xor_sync(FULLMASK, s, d);
        float mm = fmaxf(m, mo);
        s = s * __expf(m - mm) + so * __expf(mo - mm);
        m = mm;
    }
    if (lane == 0) g_rowval[row] = m + logf(s) - g_pos[row];
}

// ---------------------------------------------------------------------------
// 4) Deterministic final reduction
// ---------------------------------------------------------------------------
__global__ __launch_bounds__(256) void final_kernel(float* __restrict__ out) {
    const int t = threadIdx.x;
    float s = 0.0f;
    #pragma unroll
    for (int k = 0; k < 32; k++) s += g_rowval[k * 256 + t];
    __shared__ float sm[256];
    sm[t] = s;
    __syncthreads();
    #pragma unroll
    for (int st = 128; st > 0; st >>= 1) {
        if (t < st) sm[t] += sm[t + st];
        __syncthreads();
    }
    if (t == 0) out[0] = sm[0] / (float)NN;
}

// ---------------------------------------------------------------------------
extern "C" void kernel_launch(void* const* d_in, const int* in_sizes, int n_in,
                              void* d_out, int out_size) {
    const float* hi = (const float*)d_in[0];
    const float* hj = (const float*)d_in[1];
    float* out = (float*)d_out;

    cudaFuncSetAttribute(gemm_fused_kernel,
                         cudaFuncAttributeMaxDynamicSharedMemorySize, SMEM_BYTES);

    convert_kernel<<<(BSZ * DD / 4 + 255) / 256, 256>>>(
        (const float4*)hi, (const float4*)hj);
    gemm_fused_kernel<<<NTILES, 256, SMEM_BYTES>>>();
    combine_kernel<<<NN / 8, 256>>>();
    final_kernel<<<1, 256>>>(out);
}